// round 13
// baseline (speedup 1.0000x reference)
#include <cuda_runtime.h>
#include <cuda_bf16.h>

#define KNN 32
#define NPB 128            // atoms per molecule (contiguous, 128-aligned)
#define NODES_PER_CTA 4    // one node per warp
typedef unsigned long long u64;
typedef unsigned int u32;

__device__ __forceinline__ u64 shflx64(u64 v, int m) {
  return __shfl_xor_sync(0xFFFFFFFFu, v, m);  // 2x 32-bit SHFL.BFLY
}

// One compare-exchange step of a bitonic network on u64 keys.
__device__ __forceinline__ void cas64(u64& a, int m, bool keepMin) {
  const u64 o = shflx64(a, m);
  const bool lt = a < o;           // ISETP.U32 + ISETP.X
  a = (lt == keepMin) ? a : o;     // 2x SEL
}

// Warp-per-node radius graph, exact sorted top-32 (d2 asc, idx asc) matching
// jax.lax.top_k(-masked). d2 replicates the reference's (XLA contraction-on)
// rounding:
//   sq  = fma(z,z, fma(y,y, x*x))
//   dot = fma(z,z', fma(y,y', x*x'))
//   d2  = max((sq_i + sq_j) - 2*dot, 0)
//
// Shuffle-count optimization: a ballot/popc bisection over the VALID key
// space only (d2bits in [0, 0x41C80001); invalid candidates get kb=0xFFFFFFFF
// and never survive) finds pivot hi with survivors in [32, ~40] when the node
// has >=32 in-radius neighbors; when it has fewer, hi stays at the domain top
// and all valid keys survive. Survivors are rank-compacted into 64 shared
// slots pre-filled with fillpad=(0xFFFFFFFF<<32|self) (sorts after every
// valid key; identical pad rows make pad order irrelevant and exactly
// reproduce the reference's self-loop padding). Only TWO 32-wide bitonic
// sorts + one merge then run: 70 SHFL.32 vs 150 for the full 4-column net.
// Survivor set is downward-closed in kb, hence in (kb,idx) u64 order ->
// contains the exact top-32 including whole tie classes.
__global__ __launch_bounds__(NPB) void radius_graph_kernel(
    const float* __restrict__ pos, const int* __restrict__ batch,
    float* __restrict__ out, int N) {
  __shared__ float sx[NPB], sy[NPB], sz[NPB], ssq[NPB];
  __shared__ int sb[NPB];
  __shared__ u64 slots[NODES_PER_CTA][64];

  const int tid  = threadIdx.x;
  const int lane = tid & 31;
  const int wid  = tid >> 5;
  const int n    = blockIdx.x * NODES_PER_CTA + wid;
  const int molbase = n & ~(NPB - 1);

  // Stage the molecule's 128 atoms (one per thread).
  {
    const float ax = pos[3 * (molbase + tid) + 0];
    const float ay = pos[3 * (molbase + tid) + 1];
    const float az = pos[3 * (molbase + tid) + 2];
    sx[tid] = ax; sy[tid] = ay; sz[tid] = az;
    ssq[tid] = __fmaf_rn(az, az, __fmaf_rn(ay, ay, __fmul_rn(ax, ax)));
    sb[tid]  = batch[molbase + tid];
  }
  __syncthreads();

  const int self = n & (NPB - 1);
  const float x = sx[self], y = sy[self], z = sz[self];
  const float sq = ssq[self];
  const int bme = sb[self];

  // Candidate key high-words: column m holds j = m*32 + lane.
  u32 kb[4];
#pragma unroll
  for (int m = 0; m < 4; m++) {
    const int j = m * 32 + lane;
    const float dot =
        __fmaf_rn(z, sz[j], __fmaf_rn(y, sy[j], __fmul_rn(x, sx[j])));
    float d2 = __fsub_rn(__fadd_rn(sq, ssq[j]), __fmul_rn(2.0f, dot));
    d2 = fmaxf(d2, 0.0f);
    const bool ok = (sb[j] == bme) && (d2 <= 25.0f);
    kb[m] = ok ? __float_as_uint(d2) : 0xFFFFFFFFu;
  }

  // Branchless bisection over valid-key space [0, 0x41C80001].
  // If V>=32: invariant count(<=hi)>=32 holds; final window ~269K codes ->
  // survivors ~33-40. If V<32: no mid reaches 32, hi stays at top, all V
  // valid keys survive.
  u32 lo = 0u, hi = 0x41C80001u;
#pragma unroll
  for (int it = 0; it < 12; it++) {
    const u32 mid = (lo + hi) >> 1;
    const int c = __popc(__ballot_sync(0xFFFFFFFFu, kb[0] <= mid)) +
                  __popc(__ballot_sync(0xFFFFFFFFu, kb[1] <= mid)) +
                  __popc(__ballot_sync(0xFFFFFFFFu, kb[2] <= mid)) +
                  __popc(__ballot_sync(0xFFFFFFFFu, kb[3] <= mid));
    const bool ge = (c >= 32);
    hi = ge ? mid : hi;
    lo = ge ? lo : mid;
  }

  // Rank-compact survivors (kb <= hi) into 64 shared slots.
  u64* __restrict__ S = slots[wid];
  const u64 fillpad = (0xFFFFFFFFULL << 32) | (u32)self;
  S[lane]      = fillpad;
  S[lane + 32] = fillpad;
  __syncwarp();

  const u32 ltmask = (1u << lane) - 1u;
  int base = 0;
#pragma unroll
  for (int m = 0; m < 4; m++) {
    const bool sv = (kb[m] <= hi);
    const u32 bm = __ballot_sync(0xFFFFFFFFu, sv);
    const int r = base + __popc(bm & ltmask);
    base += __popc(bm);
    if (sv && r < 64) S[r] = (((u64)kb[m]) << 32) | (u32)(m * 32 + lane);
  }
  __syncwarp();

  u64 c0 = S[lane];
  u64 c1 = S[lane + 32];

  // Two interleaved bitonic sorts: c0 ascending, c1 descending.
#pragma unroll
  for (int k = 2; k <= 32; k <<= 1) {
#pragma unroll
    for (int j = k >> 1; j > 0; j >>= 1) {
      const bool basedir = (((lane & j) == 0) == ((lane & k) == 0));
      cas64(c0, j, basedir);
      cas64(c1, j, !basedir);
    }
  }
  // concat(asc, desc) is bitonic -> elementwise min = 32 smallest (bitonic);
  // 5-stage merge sorts ascending.
  u64 key = (c0 < c1) ? c0 : c1;
#pragma unroll
  for (int j = 16; j > 0; j >>= 1) {
    cas64(key, j, (lane & j) == 0);
  }

  // Emit slot `lane` of node n; pads carry self in the low word.
  const int j = (int)(u32)key;
  const float vx = x - sx[j];
  const float vy = y - sy[j];
  const float vz = z - sz[j];
  const float ssv = __fmaf_rn(vz, vz, __fmaf_rn(vy, vy, __fmul_rn(vx, vx)));
  const float w = (j == self) ? 0.0f : __fsqrt_rn(ssv);

  const long long NK = (long long)N * KNN;
  const int e = n * KNN + lane;
  out[e]          = (float)n;
  out[NK + e]     = (float)(molbase + j);
  out[2 * NK + e] = w;
  float* __restrict__ ov = out + 3 * NK + 3LL * e;
  ov[0] = vx; ov[1] = vy; ov[2] = vz;
}

extern "C" void kernel_launch(void* const* d_in, const int* in_sizes, int n_in,
                              void* d_out, int out_size) {
  const float* pos  = (const float*)d_in[0];
  const int* batch  = (const int*)d_in[1];
  const int N = in_sizes[0] / 3;            // pos is [N,3]
  const int nblocks = N / NODES_PER_CTA;    // one warp per node
  radius_graph_kernel<<<nblocks, NPB>>>(pos, batch, (float*)d_out, N);
}

// round 14
// speedup vs baseline: 1.0098x; 1.0098x over previous
#include <cuda_runtime.h>
#include <cuda_bf16.h>

#define KNN 32
#define NPB 128            // atoms per molecule (contiguous, 128-aligned)
#define NODES_PER_CTA 8    // 4 warps x 2 serial nodes each
typedef unsigned long long u64;
typedef unsigned int u32;

__device__ __forceinline__ u64 shflx64(u64 v, int m) {
  return __shfl_xor_sync(0xFFFFFFFFu, v, m);  // 2x 32-bit SHFL.BFLY
}

// One compare-exchange step of a bitonic network on u64 keys.
__device__ __forceinline__ void cas64(u64& a, int m, bool keepMin) {
  const u64 o = shflx64(a, m);
  const bool lt = a < o;           // ISETP.U32 + ISETP.X
  a = (lt == keepMin) ? a : o;     // 2x SEL
}

// Warp-per-node radius graph; exact sorted top-32 (d2 asc, idx asc), matching
// jax.lax.top_k(-masked). d2 replicates the reference's (XLA contraction-on)
// rounding:
//   sq  = fma(z,z, fma(y,y, x*x))
//   dot = fma(z,z', fma(y,y', x*x'))
//   d2  = max((sq_i + sq_j) - 2*dot, 0)
//
// Scheduling: each warp processes TWO nodes serially. Grid = N/8 = 1536
// blocks -> ~10.4 blocks/SM, all resident in ONE wave (16-block residency at
// 32 regs), eliminating the ~30% straggler tail that capped issue at ~66%
// for the 3072-block single-node-per-warp launch.
__global__ __launch_bounds__(NPB, 16) void radius_graph_kernel(
    const float* __restrict__ pos, const int* __restrict__ batch,
    float* __restrict__ out, int N) {
  __shared__ float sx[NPB], sy[NPB], sz[NPB], ssq[NPB];
  __shared__ int sb[NPB];

  const int tid  = threadIdx.x;
  const int lane = tid & 31;
  const int wid  = tid >> 5;
  const int nbase = blockIdx.x * NODES_PER_CTA;
  const int molbase = nbase & ~(NPB - 1);  // 8 | 128 -> one molecule per CTA

  // Stage the molecule's 128 atoms once (one per thread).
  {
    const float ax = pos[3 * (molbase + tid) + 0];
    const float ay = pos[3 * (molbase + tid) + 1];
    const float az = pos[3 * (molbase + tid) + 2];
    sx[tid] = ax; sy[tid] = ay; sz[tid] = az;
    ssq[tid] = __fmaf_rn(az, az, __fmaf_rn(ay, ay, __fmul_rn(ax, ax)));
    sb[tid]  = batch[molbase + tid];
  }
  __syncthreads();

  const long long NK = (long long)N * KNN;

#pragma unroll
  for (int p = 0; p < 2; p++) {
    const int n = nbase + wid * 2 + p;
    const int self = n & (NPB - 1);
    const float x = sx[self], y = sy[self], z = sz[self];
    const float sq = ssq[self];
    const int bme = sb[self];
    const u64 padkey = (0x7FFFFFFFULL << 32) | (u32)self;

    // Candidate keys: column m holds j = m*32 + lane.
    u64 r0, r1, r2, r3;
    {
      u64 rr[4];
#pragma unroll
      for (int m = 0; m < 4; m++) {
        const int j = m * 32 + lane;
        const float dot =
            __fmaf_rn(z, sz[j], __fmaf_rn(y, sy[j], __fmul_rn(x, sx[j])));
        float d2 = __fsub_rn(__fadd_rn(sq, ssq[j]), __fmul_rn(2.0f, dot));
        d2 = fmaxf(d2, 0.0f);
        const bool ok = (sb[j] == bme) && (d2 <= 25.0f);
        rr[m] = ok ? (((u64)__float_as_uint(d2) << 32) | (u32)j) : padkey;
      }
      r0 = rr[0]; r1 = rr[1]; r2 = rr[2]; r3 = rr[3];
    }

    // Four interleaved bitonic sorts: r0,r2 ascending; r1,r3 descending.
#pragma unroll
    for (int k = 2; k <= 32; k <<= 1) {
#pragma unroll
      for (int j = k >> 1; j > 0; j >>= 1) {
        const bool base = (((lane & j) == 0) == ((lane & k) == 0));
        cas64(r0, j, base);
        cas64(r1, j, !base);
        cas64(r2, j, base);
        cas64(r3, j, !base);
      }
    }

    // keep-low merges: concat(asc, desc) is bitonic -> elementwise min is the
    // 32 smallest; 5-stage merge sorts it. t01 ascending, t23 descending so
    // the final merge also starts with a plain min. Interleaved 2-way.
    u64 t01 = (r0 < r1) ? r0 : r1;
    u64 t23 = (r2 < r3) ? r2 : r3;
#pragma unroll
    for (int j = 16; j > 0; j >>= 1) {
      const bool up = (lane & j) == 0;
      cas64(t01, j, up);    // ascending
      cas64(t23, j, !up);   // descending
    }
    u64 key = (t01 < t23) ? t01 : t23;
#pragma unroll
    for (int j = 16; j > 0; j >>= 1) {
      cas64(key, j, (lane & j) == 0);  // ascending final
    }

    // Emit slot `lane` of node n; pads already carry self in the low word.
    const int j = (int)(u32)key;
    const float vx = x - sx[j];
    const float vy = y - sy[j];
    const float vz = z - sz[j];
    const float ssv = __fmaf_rn(vz, vz, __fmaf_rn(vy, vy, __fmul_rn(vx, vx)));
    const float w = (j == self) ? 0.0f : __fsqrt_rn(ssv);

    const int e = n * KNN + lane;
    out[e]          = (float)n;
    out[NK + e]     = (float)(molbase + j);
    out[2 * NK + e] = w;
    float* __restrict__ ov = out + 3 * NK + 3LL * e;
    ov[0] = vx; ov[1] = vy; ov[2] = vz;
  }
}

extern "C" void kernel_launch(void* const* d_in, const int* in_sizes, int n_in,
                              void* d_out, int out_size) {
  const float* pos  = (const float*)d_in[0];
  const int* batch  = (const int*)d_in[1];
  const int N = in_sizes[0] / 3;            // pos is [N,3]
  const int nblocks = N / NODES_PER_CTA;    // 1536: single resident wave
  radius_graph_kernel<<<nblocks, NPB>>>(pos, batch, (float*)d_out, N);
}